// round 16
// baseline (speedup 1.0000x reference)
#include <cuda_runtime.h>

#define TPB 128
typedef unsigned long long ull;

// x:      (4, 32, 56, 56) f32
// weight: (4, 4, 9, 8, 16) f32   [o][p][k][l][d]
// out:    (4, 64, 56, 56) f32    channel = o*16 + d
//
// Round-15 config (best known) + duplicated-pair x tile with correct bank
// geometry: tile2[s][ch] holds (v,v) float2, spatial pitch 35 (3 mod 16),
// column-major site map (warp sites distinct mod 16) -> patch loads are
// conflict-free LDS.64 broadcasts, zero pack MOVs in the priors loop.
// 2 lanes/site (d-halves), f32x2 math, base-2 softmax with max, inv folded,
// __launch_bounds__(128,3), l-loop unroll 4.

__device__ __forceinline__ ull fma2(ull a, ull b, ull c) {
    ull d;
    asm("fma.rn.f32x2 %0, %1, %2, %3;" : "=l"(d) : "l"(a), "l"(b), "l"(c));
    return d;
}
__device__ __forceinline__ ull mul2(ull a, ull b) {
    ull d;
    asm("mul.rn.f32x2 %0, %1, %2;" : "=l"(d) : "l"(a), "l"(b));
    return d;
}
__device__ __forceinline__ ull pack2(float x, float y) {
    ull r;
    asm("mov.b64 %0, {%1, %2};" : "=l"(r) : "f"(x), "f"(y));
    return r;
}
__device__ __forceinline__ float2 unpack2(ull v) {
    float2 r;
    asm("mov.b64 {%0, %1}, %2;" : "=f"(r.x), "=f"(r.y) : "l"(v));
    return r;
}
__device__ __forceinline__ float ex2(float x) {
    float r;
    asm("ex2.approx.f32 %0, %1;" : "=f"(r) : "f"(x));
    return r;
}
__device__ __forceinline__ float sqrt_approx(float x) {
    float r;
    asm("sqrt.approx.f32 %0, %1;" : "=f"(r) : "f"(x));
    return r;
}

__global__ void __launch_bounds__(TPB, 3) caps_kernel(
    const float* __restrict__ x,
    const float* __restrict__ wgt,
    float* __restrict__ out)
{
    __shared__ float sw[4608];    // weight[o]: [p][k][l][d]  (18 KB)
    __shared__ ull tile2[3500];   // x tile: [s 100][ch 32], pitch 35, (v,v) pairs

    const int o  = blockIdx.y;
    const int n  = blockIdx.z;
    const int bx = blockIdx.x;          // 0..48 : 7x7 tiles of 8x8 sites
    const int tr = bx / 7, tc = bx - tr * 7;
    const int tid = threadIdx.x;

    // ---- stage weights (1152 float4 = 9 * 128) ----
    {
        const float4* src = reinterpret_cast<const float4*>(wgt) + o * 1152;
        float4* dst = reinterpret_cast<float4*>(sw);
        #pragma unroll
        for (int i = 0; i < 9; ++i)
            dst[tid + i * TPB] = src[tid + i * TPB];
    }

    // ---- stage zero-padded, pair-duplicated x tile (3200 = 25 * 128) ----
    {
        const int h0 = tr * 8 - 1, w0 = tc * 8 - 1;
        const float* xb = x + n * 32 * 3136;
        #pragma unroll
        for (int i = 0; i < 25; ++i) {
            const int idx = tid + i * TPB;
            const int ch  = idx / 100;            // 0..31
            const int sp  = idx - ch * 100;       // 0..99 spatial
            const int rr  = sp / 10;
            const int cc  = sp - rr * 10;
            const int gh = h0 + rr, gw = w0 + cc;
            float v = 0.0f;
            if ((unsigned)gh < 56u && (unsigned)gw < 56u)
                v = __ldg(xb + ch * 3136 + gh * 56 + gw);
            tile2[sp * 35 + ch] = pack2(v, v);
        }
    }
    __syncthreads();

    const int half = tid & 1;           // 8-d half owned
    const int si   = tid >> 1;          // 0..63 site within tile
    const int r = si & 7, c = si >> 3;  // COLUMN-major map (bank-distinct s)
    const int s = (tr * 8 + r) * 56 + (tc * 8 + c);

    ull outs[4];
    #pragma unroll
    for (int j = 0; j < 4; ++j) outs[j] = 0ull;

    const ulonglong2* swu2 = reinterpret_cast<const ulonglong2*>(sw);
    const int tcen = ((r + 1) * 10 + (c + 1)) * 35;   // center entry (pitch 35)
    const float LOG2E = 1.44269504f;

    #pragma unroll 1
    for (int p = 0; p < 4; ++p) {
        // ---- priors[k][own 8 d's] as 4 f32x2 pairs per k ----
        ull pri[36];

        #pragma unroll 4
        for (int l = 0; l < 8; ++l) {
            const ull* tl = tile2 + tcen + (p * 8 + l);
            ull pt[9];
            pt[0] = tl[-385]; pt[1] = tl[-350]; pt[2] = tl[-315];
            pt[3] = tl[-35];  pt[4] = tl[0];    pt[5] = tl[35];
            pt[6] = tl[315];  pt[7] = tl[350];  pt[8] = tl[385];

            const ulonglong2* wb = swu2 + (p * 72 + l) * 4 + half * 2;
            if (l == 0) {
                #pragma unroll
                for (int k = 0; k < 9; ++k) {
                    const ulonglong2 wa = wb[k * 32];
                    const ulonglong2 wc = wb[k * 32 + 1];
                    pri[k*4 + 0] = mul2(pt[k], wa.x);
                    pri[k*4 + 1] = mul2(pt[k], wa.y);
                    pri[k*4 + 2] = mul2(pt[k], wc.x);
                    pri[k*4 + 3] = mul2(pt[k], wc.y);
                }
            } else {
                #pragma unroll
                for (int k = 0; k < 9; ++k) {
                    const ulonglong2 wa = wb[k * 32];
                    const ulonglong2 wc = wb[k * 32 + 1];
                    pri[k*4 + 0] = fma2(pt[k], wa.x, pri[k*4 + 0]);
                    pri[k*4 + 1] = fma2(pt[k], wa.y, pri[k*4 + 1]);
                    pri[k*4 + 2] = fma2(pt[k], wc.x, pri[k*4 + 2]);
                    pri[k*4 + 3] = fma2(pt[k], wc.y, pri[k*4 + 3]);
                }
            }
        }

        // ---- dynamic routing (logits in base-2 domain) ----
        float logits[9];

        // ===== iteration 0: logits all zero -> probs exactly uniform =====
        {
            const ull np = pack2(0.1111111111f, 0.1111111111f);
            ull sv[4];
            #pragma unroll
            for (int j = 0; j < 4; ++j) sv[j] = mul2(np, pri[j]);
            #pragma unroll
            for (int k = 1; k < 9; ++k) {
                #pragma unroll
                for (int j = 0; j < 4; ++j)
                    sv[j] = fma2(np, pri[k*4 + j], sv[j]);
            }

            ull acc = mul2(sv[0], sv[0]);
            #pragma unroll
            for (int j = 1; j < 4; ++j) acc = fma2(sv[j], sv[j], acc);
            const float2 a2 = unpack2(acc);
            const float sqo = a2.x + a2.y;
            const float sq = sqo + __shfl_xor_sync(0xffffffffu, sqo, 1);
            const float f = sqrt_approx(sq) * __fdividef(1.0f, 1.0f + sq);
            const float fs = f * LOG2E;

            #pragma unroll
            for (int k = 0; k < 9; ++k) {
                ull da = mul2(pri[k*4], sv[0]);
                #pragma unroll
                for (int j = 1; j < 4; ++j)
                    da = fma2(pri[k*4 + j], sv[j], da);
                const float2 d2 = unpack2(da);
                const float dlo = d2.x + d2.y;
                const float dl = dlo + __shfl_xor_sync(0xffffffffu, dlo, 1);
                logits[k] = fs * dl;
            }
        }

        // ===== iterations 1 and 2 (softmax with max; inv folded into squash) =====
        #pragma unroll 1
        for (int it = 1; it < 3; ++it) {
            float mx = logits[0];
            #pragma unroll
            for (int k = 1; k < 9; ++k) mx = fmaxf(mx, logits[k]);
            float pr[9];
            float sum = 0.0f;
            #pragma unroll
            for (int k = 0; k < 9; ++k) {
                pr[k] = ex2(logits[k] - mx);
                sum += pr[k];
            }
            const float inv = __fdividef(1.0f, sum);

            // sv_un = sum_k pr[k] * pri[k]   (unnormalized; true s = inv * sv_un)
            ull sv[4];
            {
                const ull pkk0 = pack2(pr[0], pr[0]);
                #pragma unroll
                for (int j = 0; j < 4; ++j) sv[j] = mul2(pkk0, pri[j]);
            }
            #pragma unroll
            for (int k = 1; k < 9; ++k) {
                const ull pkk = pack2(pr[k], pr[k]);
                #pragma unroll
                for (int j = 0; j < 4; ++j)
                    sv[j] = fma2(pkk, pri[k*4 + j], sv[j]);
            }

            ull acc = mul2(sv[0], sv[0]);
            #pragma unroll
            for (int j = 1; j < 4; ++j) acc = fma2(sv[j], sv[j], acc);
            const float2 a2 = unpack2(acc);
            const float sqo = a2.x + a2.y;
            const float squ = sqo + __shfl_xor_sync(0xffffffffu, sqo, 1);
            const float sqt = squ * inv * inv;                  // true |s|^2
            const float f = sqrt_approx(sqt) * __fdividef(1.0f, 1.0f + sqt);
            const float fi = f * inv;

            if (it == 1) {
                // true increment = LOG2E * f * inv * dl_un
                const float fs = fi * LOG2E;
                #pragma unroll
                for (int k = 0; k < 9; ++k) {
                    ull da = mul2(pri[k*4], sv[0]);
                    #pragma unroll
                    for (int j = 1; j < 4; ++j)
                        da = fma2(pri[k*4 + j], sv[j], da);
                    const float2 d2 = unpack2(da);
                    const float dlo = d2.x + d2.y;
                    const float dl = dlo + __shfl_xor_sync(0xffffffffu, dlo, 1);
                    logits[k] = fmaf(fs, dl, logits[k]);
                }
            } else {
                const ull ff = pack2(fi, fi);
                #pragma unroll
                for (int j = 0; j < 4; ++j)
                    outs[j] = fma2(sv[j], ff, outs[j]);
            }
        }
    }

    // ---- write: out[n][o*16 + half*8 + j][h][w] ----
    float* ob = out + ((n * 4 + o) * 16 + half * 8) * 3136 + s;
    #pragma unroll
    for (int j = 0; j < 4; ++j) {
        const float2 v = unpack2(outs[j]);
        ob[(2*j    ) * 3136] = v.x;
        ob[(2*j + 1) * 3136] = v.y;
    }
}

extern "C" void kernel_launch(void* const* d_in, const int* in_sizes, int n_in,
                              void* d_out, int out_size) {
    const float* x   = (const float*)d_in[0];
    const float* wgt = (const float*)d_in[1];
    float* out = (float*)d_out;

    dim3 grid(49, 4, 4);  // 7x7 spatial tiles, o=4, n=4
    caps_kernel<<<grid, TPB>>>(x, wgt, out);
}

// round 17
// speedup vs baseline: 1.1395x; 1.1395x over previous
#include <cuda_runtime.h>

#define TPB 128
typedef unsigned long long ull;

// x:      (4, 32, 56, 56) f32
// weight: (4, 4, 9, 8, 16) f32   [o][p][k][l][d]
// out:    (4, 64, 56, 56) f32    channel = o*16 + d
//
// Best-known configuration (round 15): block = 8x8 spatial tile, 2 lanes
// per site (d-halves), f32x2 packed math, scalar zero-padded smem x tile,
// weights in smem, base-2 softmax with max, inv folded into squash scales,
// __launch_bounds__(128, 3) (no-spill point: ~167 regs, 12 warps/SM).
// Single change vs round 15: l-loop fully unrolled (8) for maximum LDS MLP.

__device__ __forceinline__ ull fma2(ull a, ull b, ull c) {
    ull d;
    asm("fma.rn.f32x2 %0, %1, %2, %3;" : "=l"(d) : "l"(a), "l"(b), "l"(c));
    return d;
}
__device__ __forceinline__ ull mul2(ull a, ull b) {
    ull d;
    asm("mul.rn.f32x2 %0, %1, %2;" : "=l"(d) : "l"(a), "l"(b));
    return d;
}
__device__ __forceinline__ ull pack2(float x, float y) {
    ull r;
    asm("mov.b64 %0, {%1, %2};" : "=l"(r) : "f"(x), "f"(y));
    return r;
}
__device__ __forceinline__ float2 unpack2(ull v) {
    float2 r;
    asm("mov.b64 {%0, %1}, %2;" : "=f"(r.x), "=f"(r.y) : "l"(v));
    return r;
}
__device__ __forceinline__ float ex2(float x) {
    float r;
    asm("ex2.approx.f32 %0, %1;" : "=f"(r) : "f"(x));
    return r;
}
__device__ __forceinline__ float sqrt_approx(float x) {
    float r;
    asm("sqrt.approx.f32 %0, %1;" : "=f"(r) : "f"(x));
    return r;
}

__global__ void __launch_bounds__(TPB, 3) caps_kernel(
    const float* __restrict__ x,
    const float* __restrict__ wgt,
    float* __restrict__ out)
{
    __shared__ float sw[4608];    // weight[o]: [p][k][l][d]  (18 KB)
    __shared__ float tile[3200];  // x tile: [ch 32][row 10][col 10], zero-padded

    const int o  = blockIdx.y;
    const int n  = blockIdx.z;
    const int bx = blockIdx.x;          // 0..48 : 7x7 tiles of 8x8 sites
    const int tr = bx / 7, tc = bx - tr * 7;
    const int tid = threadIdx.x;

    // ---- stage weights (1152 float4 = 9 * 128) ----
    {
        const float4* src = reinterpret_cast<const float4*>(wgt) + o * 1152;
        float4* dst = reinterpret_cast<float4*>(sw);
        #pragma unroll
        for (int i = 0; i < 9; ++i)
            dst[tid + i * TPB] = src[tid + i * TPB];
    }

    // ---- stage zero-padded x tile (3200 = 25 * 128) ----
    {
        const int h0 = tr * 8 - 1, w0 = tc * 8 - 1;
        const float* xb = x + n * 32 * 3136;
        #pragma unroll
        for (int i = 0; i < 25; ++i) {
            const int idx = tid + i * TPB;
            const int ch  = idx / 100;
            const int rem = idx - ch * 100;
            const int rr  = rem / 10;
            const int cc  = rem - rr * 10;
            const int gh = h0 + rr, gw = w0 + cc;
            float v = 0.0f;
            if ((unsigned)gh < 56u && (unsigned)gw < 56u)
                v = __ldg(xb + ch * 3136 + gh * 56 + gw);
            tile[idx] = v;
        }
    }
    __syncthreads();

    const int half = tid & 1;           // 8-d half owned
    const int si   = tid >> 1;          // 0..63 site within tile
    const int r = si >> 3, c = si & 7;
    const int s = (tr * 8 + r) * 56 + (tc * 8 + c);

    ull outs[4];
    #pragma unroll
    for (int j = 0; j < 4; ++j) outs[j] = 0ull;

    const ulonglong2* swu2 = reinterpret_cast<const ulonglong2*>(sw);
    const int tbase = (r + 1) * 10 + (c + 1);
    const float LOG2E = 1.44269504f;

    #pragma unroll 1
    for (int p = 0; p < 4; ++p) {
        // ---- priors[k][own 8 d's] as 4 f32x2 pairs per k ----
        ull pri[36];

        #pragma unroll 8
        for (int l = 0; l < 8; ++l) {
            const float* tl = &tile[(p * 8 + l) * 100 + tbase];
            float pt[9];
            pt[0] = tl[-11]; pt[1] = tl[-10]; pt[2] = tl[-9];
            pt[3] = tl[-1];  pt[4] = tl[0];   pt[5] = tl[1];
            pt[6] = tl[9];   pt[7] = tl[10];  pt[8] = tl[11];

            const ulonglong2* wb = swu2 + (p * 72 + l) * 4 + half * 2;
            if (l == 0) {
                #pragma unroll
                for (int k = 0; k < 9; ++k) {
                    const ulonglong2 wa = wb[k * 32];
                    const ulonglong2 wc = wb[k * 32 + 1];
                    const ull pkk = pack2(pt[k], pt[k]);
                    pri[k*4 + 0] = mul2(pkk, wa.x);
                    pri[k*4 + 1] = mul2(pkk, wa.y);
                    pri[k*4 + 2] = mul2(pkk, wc.x);
                    pri[k*4 + 3] = mul2(pkk, wc.y);
                }
            } else {
                #pragma unroll
                for (int k = 0; k < 9; ++k) {
                    const ulonglong2 wa = wb[k * 32];
                    const ulonglong2 wc = wb[k * 32 + 1];
                    const ull pkk = pack2(pt[k], pt[k]);
                    pri[k*4 + 0] = fma2(pkk, wa.x, pri[k*4 + 0]);
                    pri[k*4 + 1] = fma2(pkk, wa.y, pri[k*4 + 1]);
                    pri[k*4 + 2] = fma2(pkk, wc.x, pri[k*4 + 2]);
                    pri[k*4 + 3] = fma2(pkk, wc.y, pri[k*4 + 3]);
                }
            }
        }

        // ---- dynamic routing (logits in base-2 domain) ----
        float logits[9];

        // ===== iteration 0: logits all zero -> probs exactly uniform =====
        {
            const ull np = pack2(0.1111111111f, 0.1111111111f);
            ull sv[4];
            #pragma unroll
            for (int j = 0; j < 4; ++j) sv[j] = mul2(np, pri[j]);
            #pragma unroll
            for (int k = 1; k < 9; ++k) {
                #pragma unroll
                for (int j = 0; j < 4; ++j)
                    sv[j] = fma2(np, pri[k*4 + j], sv[j]);
            }

            ull acc = mul2(sv[0], sv[0]);
            #pragma unroll
            for (int j = 1; j < 4; ++j) acc = fma2(sv[j], sv[j], acc);
            const float2 a2 = unpack2(acc);
            const float sqo = a2.x + a2.y;
            const float sq = sqo + __shfl_xor_sync(0xffffffffu, sqo, 1);
            const float f = sqrt_approx(sq) * __fdividef(1.0f, 1.0f + sq);
            const float fs = f * LOG2E;

            #pragma unroll
            for (int k = 0; k < 9; ++k) {
                ull da = mul2(pri[k*4], sv[0]);
                #pragma unroll
                for (int j = 1; j < 4; ++j)
                    da = fma2(pri[k*4 + j], sv[j], da);
                const float2 d2 = unpack2(da);
                const float dlo = d2.x + d2.y;
                const float dl = dlo + __shfl_xor_sync(0xffffffffu, dlo, 1);
                logits[k] = fs * dl;
            }
        }

        // ===== iterations 1 and 2 (softmax with max; inv folded into squash) =====
        #pragma unroll 1
        for (int it = 1; it < 3; ++it) {
            float mx = logits[0];
            #pragma unroll
            for (int k = 1; k < 9; ++k) mx = fmaxf(mx, logits[k]);
            float pr[9];
            float sum = 0.0f;
            #pragma unroll
            for (int k = 0; k < 9; ++k) {
                pr[k] = ex2(logits[k] - mx);
                sum += pr[k];
            }
            const float inv = __fdividef(1.0f, sum);

            // sv_un = sum_k pr[k] * pri[k]   (unnormalized; true s = inv * sv_un)
            ull sv[4];
            {
                const ull pkk0 = pack2(pr[0], pr[0]);
                #pragma unroll
                for (int j = 0; j < 4; ++j) sv[j] = mul2(pkk0, pri[j]);
            }
            #pragma unroll
            for (int k = 1; k < 9; ++k) {
                const ull pkk = pack2(pr[k], pr[k]);
                #pragma unroll
                for (int j = 0; j < 4; ++j)
                    sv[j] = fma2(pkk, pri[k*4 + j], sv[j]);
            }

            ull acc = mul2(sv[0], sv[0]);
            #pragma unroll
            for (int j = 1; j < 4; ++j) acc = fma2(sv[j], sv[j], acc);
            const float2 a2 = unpack2(acc);
            const float sqo = a2.x + a2.y;
            const float squ = sqo + __shfl_xor_sync(0xffffffffu, sqo, 1);
            const float sqt = squ * inv * inv;                  // true |s|^2
            const float f = sqrt_approx(sqt) * __fdividef(1.0f, 1.0f + sqt);
            const float fi = f * inv;

            if (it == 1) {
                // true increment = LOG2E * f * inv * dl_un
                const float fs = fi * LOG2E;
                #pragma unroll
                for (int k = 0; k < 9; ++k) {
                    ull da = mul2(pri[k*4], sv[0]);
                    #pragma unroll
                    for (int j = 1; j < 4; ++j)
                        da = fma2(pri[k*4 + j], sv[j], da);
                    const float2 d2 = unpack2(da);
                    const float dlo = d2.x + d2.y;
                    const float dl = dlo + __shfl_xor_sync(0xffffffffu, dlo, 1);
                    logits[k] = fmaf(fs, dl, logits[k]);
                }
            } else {
                const ull ff = pack2(fi, fi);
                #pragma unroll
                for (int j = 0; j < 4; ++j)
                    outs[j] = fma2(sv[j], ff, outs[j]);
            }
        }
    }

    // ---- write: out[n][o*16 + half*8 + j][h][w] ----
    float* ob = out + ((n * 4 + o) * 16 + half * 8) * 3136 + s;
    #pragma unroll
    for (int j = 0; j < 4; ++j) {
        const float2 v = unpack2(outs[j]);
        ob[(2*j    ) * 3136] = v.x;
        ob[(2*j + 1) * 3136] = v.y;
    }
}

extern "C" void kernel_launch(void* const* d_in, const int* in_sizes, int n_in,
                              void* d_out, int out_size) {
    const float* x   = (const float*)d_in[0];
    const float* wgt = (const float*)d_in[1];
    float* out = (float*)d_out;

    dim3 grid(49, 4, 4);  // 7x7 spatial tiles, o=4, n=4
    caps_kernel<<<grid, TPB>>>(x, wgt, out);
}